// round 4
// baseline (speedup 1.0000x reference)
#include <cuda_runtime.h>
#include <math.h>

#define H 256
#define DIN 700
#define DOUT 20
#define BATCH 128
#define TT 250

// Scratch (device globals: allocation-free rule)
__device__ float g_X1[(size_t)BATCH * TT * H];   // x@Wi1.T + bi1 + b11, [B*T, 256]
__device__ float g_W11T[H * H];
__device__ float g_W12T[H * H];
__device__ float g_W22T[H * H];

// ---------------------------------------------------------------------------
// Packed fp32x2 FMA helpers (sm_103a FFMA2 — only reachable via PTX)
// ---------------------------------------------------------------------------
__device__ __forceinline__ void ffma2(unsigned long long& acc,
                                      unsigned long long a,
                                      unsigned long long b) {
    asm("fma.rn.f32x2 %0, %1, %2, %0;" : "+l"(acc) : "l"(a), "l"(b));
}
__device__ __forceinline__ unsigned long long pack2(float lo, float hi) {
    unsigned long long r;
    asm("mov.b64 %0, {%1, %2};" : "=l"(r) : "f"(lo), "f"(hi));
    return r;
}
__device__ __forceinline__ void unpack2(unsigned long long v, float& lo, float& hi) {
    asm("mov.b64 {%0, %1}, %2;" : "=f"(lo), "=f"(hi) : "l"(v));
}

// ---------------------------------------------------------------------------
// Weight transpose: WT[j][i] = W[i][j] so a spike j reads a coalesced row.
// ---------------------------------------------------------------------------
__global__ void transpose_weights_kernel(const float* __restrict__ W11,
                                         const float* __restrict__ W12,
                                         const float* __restrict__ W22) {
    int idx = blockIdx.x * blockDim.x + threadIdx.x;   // 3*65536 threads
    int m = idx >> 16;
    int r = (idx >> 8) & 255;   // source row i
    int c = idx & 255;          // source col j
    if (m == 0)      g_W11T[c * H + r] = W11[r * H + c];
    else if (m == 1) g_W12T[c * H + r] = W12[r * H + c];
    else             g_W22T[c * H + r] = W22[r * H + c];
}

// ---------------------------------------------------------------------------
// X1 = x @ Wi1.T + (bi1 + b11).  M=32000, N=256, K=700.
// 128x128 tile, BK=16, double-buffered, 8x8/thread via FFMA2.
// ---------------------------------------------------------------------------
#define GBM 128
#define GBN 128
#define GBK 16
#define GPAD 4
#define GNT ((DIN + GBK - 1) / GBK)   // 44 tiles (last partial: 12 cols)

__global__ __launch_bounds__(256) void gemm_x1_kernel(
    const float* __restrict__ x, const float* __restrict__ Wi1,
    const float* __restrict__ bi1, const float* __restrict__ b11) {
    __shared__ float As[2][GBK][GBM + GPAD];
    __shared__ float Bs[2][GBK][GBN + GPAD];

    int tid = threadIdx.x;
    int m0 = blockIdx.y * GBM;
    int n0 = blockIdx.x * GBN;
    int tx = tid & 15, ty = tid >> 4;

    int row0 = tid >> 2,          kc0 = tid & 3;
    int row1 = (256 + tid) >> 2,  kc1 = tid & 3;

    unsigned long long acc[4][8];
#pragma unroll
    for (int r = 0; r < 4; ++r)
#pragma unroll
        for (int c = 0; c < 8; ++c) acc[r][c] = 0ull;

    float4 stA0, stA1, stB0, stB1;

    {
        int kA0 = kc0 * 4, kA1 = kc1 * 4;
        stA0 = *(const float4*)(x   + (size_t)(m0 + row0) * DIN + kA0);
        stA1 = *(const float4*)(x   + (size_t)(m0 + row1) * DIN + kA1);
        stB0 = *(const float4*)(Wi1 + (size_t)(n0 + row0) * DIN + kA0);
        stB1 = *(const float4*)(Wi1 + (size_t)(n0 + row1) * DIN + kA1);
        As[0][kc0 * 4 + 0][row0] = stA0.x; As[0][kc0 * 4 + 1][row0] = stA0.y;
        As[0][kc0 * 4 + 2][row0] = stA0.z; As[0][kc0 * 4 + 3][row0] = stA0.w;
        As[0][kc1 * 4 + 0][row1] = stA1.x; As[0][kc1 * 4 + 1][row1] = stA1.y;
        As[0][kc1 * 4 + 2][row1] = stA1.z; As[0][kc1 * 4 + 3][row1] = stA1.w;
        Bs[0][kc0 * 4 + 0][row0] = stB0.x; Bs[0][kc0 * 4 + 1][row0] = stB0.y;
        Bs[0][kc0 * 4 + 2][row0] = stB0.z; Bs[0][kc0 * 4 + 3][row0] = stB0.w;
        Bs[0][kc1 * 4 + 0][row1] = stB1.x; Bs[0][kc1 * 4 + 1][row1] = stB1.y;
        Bs[0][kc1 * 4 + 2][row1] = stB1.z; Bs[0][kc1 * 4 + 3][row1] = stB1.w;
    }
    __syncthreads();

    for (int t = 0; t < GNT; ++t) {
        int buf = t & 1;

        if (t + 1 < GNT) {
            int kb = (t + 1) * GBK;
            int kA0 = kb + kc0 * 4, kA1 = kb + kc1 * 4;
            stA0 = (kA0 < DIN) ? *(const float4*)(x + (size_t)(m0 + row0) * DIN + kA0)
                               : make_float4(0.f, 0.f, 0.f, 0.f);
            stA1 = (kA1 < DIN) ? *(const float4*)(x + (size_t)(m0 + row1) * DIN + kA1)
                               : make_float4(0.f, 0.f, 0.f, 0.f);
            stB0 = (kA0 < DIN) ? *(const float4*)(Wi1 + (size_t)(n0 + row0) * DIN + kA0)
                               : make_float4(0.f, 0.f, 0.f, 0.f);
            stB1 = (kA1 < DIN) ? *(const float4*)(Wi1 + (size_t)(n0 + row1) * DIN + kA1)
                               : make_float4(0.f, 0.f, 0.f, 0.f);
        }

#pragma unroll
        for (int kk = 0; kk < GBK; ++kk) {
            ulonglong2 aA = *(const ulonglong2*)&As[buf][kk][ty * 8];
            ulonglong2 aB = *(const ulonglong2*)&As[buf][kk][ty * 8 + 4];
            float4 b0 = *(const float4*)&Bs[buf][kk][tx * 8];
            float4 b1 = *(const float4*)&Bs[buf][kk][tx * 8 + 4];
            float barr[8] = {b0.x, b0.y, b0.z, b0.w, b1.x, b1.y, b1.z, b1.w};
#pragma unroll
            for (int c = 0; c < 8; ++c) {
                unsigned long long bb = pack2(barr[c], barr[c]);
                ffma2(acc[0][c], aA.x, bb);
                ffma2(acc[1][c], aA.y, bb);
                ffma2(acc[2][c], aB.x, bb);
                ffma2(acc[3][c], aB.y, bb);
            }
        }

        if (t + 1 < GNT) {
            int nb = buf ^ 1;
            As[nb][kc0 * 4 + 0][row0] = stA0.x; As[nb][kc0 * 4 + 1][row0] = stA0.y;
            As[nb][kc0 * 4 + 2][row0] = stA0.z; As[nb][kc0 * 4 + 3][row0] = stA0.w;
            As[nb][kc1 * 4 + 0][row1] = stA1.x; As[nb][kc1 * 4 + 1][row1] = stA1.y;
            As[nb][kc1 * 4 + 2][row1] = stA1.z; As[nb][kc1 * 4 + 3][row1] = stA1.w;
            Bs[nb][kc0 * 4 + 0][row0] = stB0.x; Bs[nb][kc0 * 4 + 1][row0] = stB0.y;
            Bs[nb][kc0 * 4 + 2][row0] = stB0.z; Bs[nb][kc0 * 4 + 3][row0] = stB0.w;
            Bs[nb][kc1 * 4 + 0][row1] = stB1.x; Bs[nb][kc1 * 4 + 1][row1] = stB1.y;
            Bs[nb][kc1 * 4 + 2][row1] = stB1.z; Bs[nb][kc1 * 4 + 3][row1] = stB1.w;
        }
        __syncthreads();
    }

    float bias[8];
#pragma unroll
    for (int c = 0; c < 8; ++c) {
        int n = n0 + tx * 8 + c;
        bias[c] = bi1[n] + b11[n];
    }
#pragma unroll
    for (int r2 = 0; r2 < 4; ++r2) {
        float lo[8], hi[8];
#pragma unroll
        for (int c = 0; c < 8; ++c) unpack2(acc[r2][c], lo[c], hi[c]);
        int mA = m0 + ty * 8 + 2 * r2;
        int mB = mA + 1;
        int n = n0 + tx * 8;
        float4* pA = (float4*)(g_X1 + (size_t)mA * H + n);
        float4* pB = (float4*)(g_X1 + (size_t)mB * H + n);
        pA[0] = make_float4(lo[0] + bias[0], lo[1] + bias[1], lo[2] + bias[2], lo[3] + bias[3]);
        pA[1] = make_float4(lo[4] + bias[4], lo[5] + bias[5], lo[6] + bias[6], lo[7] + bias[7]);
        pB[0] = make_float4(hi[0] + bias[0], hi[1] + bias[1], hi[2] + bias[2], hi[3] + bias[3]);
        pB[1] = make_float4(hi[4] + bias[4], hi[5] + bias[5], hi[6] + bias[6], hi[7] + bias[7]);
    }
}

// ---------------------------------------------------------------------------
// Warp-autonomous RNN. One warp = one sample. Lane owns neurons
// [8*lane, 8*lane+8). Spike vector = 8 ballot words (uniform in registers).
// Zero __syncthreads in the time loop; no lists, no SMEM partials.
// Mask word k, bit l  <->  neuron j = 8*l + k.
// ---------------------------------------------------------------------------
__device__ __forceinline__ void acc_rows4(const float* __restrict__ W,
                                          const int* js, int n, float h[8], int off) {
    float4 a[4][2];
#pragma unroll
    for (int q = 0; q < 4; ++q)
        if (q < n) {
            const float4* p = (const float4*)(W + js[q] * H + off);
            a[q][0] = p[0];
            a[q][1] = p[1];
        }
#pragma unroll
    for (int q = 0; q < 4; ++q)
        if (q < n) {
            h[0] += a[q][0].x; h[1] += a[q][0].y; h[2] += a[q][0].z; h[3] += a[q][0].w;
            h[4] += a[q][1].x; h[5] += a[q][1].y; h[6] += a[q][1].z; h[7] += a[q][1].w;
        }
}

__device__ __forceinline__ void gather_mask(const float* __restrict__ W,
                                            const unsigned m[8], float h[8], int off) {
    int js[4];
    int nb = 0;
#pragma unroll
    for (int k = 0; k < 8; ++k) {
        unsigned mm = m[k];
        while (mm) {
            int l = __ffs(mm) - 1;
            mm &= mm - 1;
            js[nb++] = (l << 3) + k;
            if (nb == 4) { acc_rows4(W, js, 4, h, off); nb = 0; }
        }
    }
    if (nb) acc_rows4(W, js, nb, h, off);
}

__global__ __launch_bounds__(128) void rnn_kernel(
    const float* __restrict__ mem1_0, const float* __restrict__ mem2_0,
    const float* __restrict__ memo_0,
    const float* __restrict__ b12v, const float* __restrict__ b22v,
    const float* __restrict__ Wo, const float* __restrict__ bov,
    const float* __restrict__ tau_adp1, const float* __restrict__ tau_adp2,
    const float* __restrict__ tau_m1, const float* __restrict__ tau_m2,
    const float* __restrict__ tau_mo,
    float* __restrict__ out) {
    __shared__ float sWoT[H * DOUT];   // WoT[j][k] = Wo[k][j], 20 KB

    int tid = threadIdx.x;
    int lane = tid & 31, warp = tid >> 5;
    int s = blockIdx.x * 4 + warp;     // sample
    int off = lane * 8;                // first owned neuron

    // WoT into SMEM (one-time)
    for (int idx = tid; idx < H * DOUT; idx += 128) {
        int j = idx / DOUT, k = idx - j * DOUT;
        sWoT[idx] = Wo[k * H + j];
    }
    __syncthreads();   // only barrier in the kernel

    // ---- per-neuron state (8 neurons per lane) ----
    float mem1[8], ab1[8], al1[8], ro1[8];
    float mem2[8], ab2[8], al2[8], ro2[8];
    float hb2c[8];
    {
        const float4* p0 = (const float4*)(mem1_0 + s * H + off);
        float4 v0 = p0[0], v1 = p0[1];
        mem1[0]=v0.x; mem1[1]=v0.y; mem1[2]=v0.z; mem1[3]=v0.w;
        mem1[4]=v1.x; mem1[5]=v1.y; mem1[6]=v1.z; mem1[7]=v1.w;
        const float4* p1 = (const float4*)(mem2_0 + s * H + off);
        float4 w0 = p1[0], w1 = p1[1];
        mem2[0]=w0.x; mem2[1]=w0.y; mem2[2]=w0.z; mem2[3]=w0.w;
        mem2[4]=w1.x; mem2[5]=w1.y; mem2[6]=w1.z; mem2[7]=w1.w;
    }
#pragma unroll
    for (int k = 0; k < 8; ++k) {
        int i = off + k;
        ab1[k] = 0.01f; ab2[k] = 0.01f;
        al1[k] = expf(-1.f / tau_m1[i]);
        ro1[k] = expf(-1.f / tau_adp1[i]);
        al2[k] = expf(-1.f / tau_m2[i]);
        ro2[k] = expf(-1.f / tau_adp2[i]);
        hb2c[k] = b12v[i] + b22v[i];
    }

    float memo = 0.f, alo = 0.f, omo = 0.f, bok = 0.f, accv = 0.f;
    if (lane < DOUT) {
        memo = memo_0[s * DOUT + lane];
        alo = expf(-1.f / tau_mo[lane]);
        omo = 1.f - alo;
        bok = bov[lane];
    }

    unsigned m1[8], m2[8];
#pragma unroll
    for (int k = 0; k < 8; ++k) { m1[k] = 0u; m2[k] = 0u; }
    unsigned sp1b = 0u, sp2b = 0u;     // per-thread spike bits (bit k)

    const float* X1base = g_X1 + (size_t)s * TT * H;

    // X1 prefetch
    float4 xc0, xc1;
    {
        const float4* p = (const float4*)(X1base + off);
        xc0 = p[0]; xc1 = p[1];
    }

    for (int t = 0; t < TT; ++t) {
        // prefetch next step's X1
        float4 xn0, xn1;
        if (t + 1 < TT) {
            const float4* p = (const float4*)(X1base + (t + 1) * H + off);
            xn0 = p[0]; xn1 = p[1];
        } else {
            xn0 = make_float4(0.f,0.f,0.f,0.f); xn1 = xn0;
        }

        // ---- phase A: W11 (old sp1) and W22 (old sp2) gathers ----
        float h1[8] = {xc0.x, xc0.y, xc0.z, xc0.w, xc1.x, xc1.y, xc1.z, xc1.w};
        float h2[8] = {hb2c[0], hb2c[1], hb2c[2], hb2c[3],
                       hb2c[4], hb2c[5], hb2c[6], hb2c[7]};
        gather_mask(g_W11T, m1, h1, off);
        gather_mask(g_W22T, m2, h2, off);

        // ---- layer 1 update + ballot masks ----
        unsigned nsp1 = 0u;
#pragma unroll
        for (int k = 0; k < 8; ++k) {
            float sk = (sp1b >> k) & 1 ? 1.f : 0.f;
            ab1[k] = ro1[k] * ab1[k] + (1.f - ro1[k]) * sk;
            float B = 0.01f + 1.8f * ab1[k];
            mem1[k] = mem1[k] * al1[k] + (1.f - al1[k]) * h1[k] - B * sk;
            if (mem1[k] - B > 0.f) nsp1 |= 1u << k;
        }
        sp1b = nsp1;
#pragma unroll
        for (int k = 0; k < 8; ++k)
            m1[k] = __ballot_sync(0xffffffffu, (nsp1 >> k) & 1);

        // ---- phase B: W12 gather (new sp1) ----
        gather_mask(g_W12T, m1, h2, off);

        // ---- layer 2 update + ballot masks ----
        unsigned nsp2 = 0u;
#pragma unroll
        for (int k = 0; k < 8; ++k) {
            float sk = (sp2b >> k) & 1 ? 1.f : 0.f;
            ab2[k] = ro2[k] * ab2[k] + (1.f - ro2[k]) * sk;
            float B = 0.01f + 1.8f * ab2[k];
            mem2[k] = mem2[k] * al2[k] + (1.f - al2[k]) * h2[k] - B * sk;
            if (mem2[k] - B > 0.f) nsp2 |= 1u << k;
        }
        sp2b = nsp2;
#pragma unroll
        for (int k = 0; k < 8; ++k)
            m2[k] = __ballot_sync(0xffffffffu, (nsp2 >> k) & 1);

        // ---- output layer (sp2 new) + softmax accumulation ----
        {
            int kk = lane < DOUT ? lane : 0;
            float o = bok;
#pragma unroll
            for (int k = 0; k < 8; ++k) {
                unsigned mm = m2[k];
                while (mm) {
                    int l = __ffs(mm) - 1;
                    mm &= mm - 1;
                    o += sWoT[((l << 3) + k) * DOUT + kk];
                }
            }
            memo = memo * alo + omo * o;
            float mv = lane < DOUT ? memo : -INFINITY;
#pragma unroll
            for (int sh = 16; sh > 0; sh >>= 1)
                mv = fmaxf(mv, __shfl_xor_sync(0xffffffffu, mv, sh));
            float e = lane < DOUT ? expf(memo - mv) : 0.f;
            float ss = e;
#pragma unroll
            for (int sh = 16; sh > 0; sh >>= 1)
                ss += __shfl_xor_sync(0xffffffffu, ss, sh);
            if (t > 10) accv += e / ss;
        }

        xc0 = xn0; xc1 = xn1;
    }

    if (lane < DOUT) out[s * DOUT + lane] = accv;
}

// ---------------------------------------------------------------------------
extern "C" void kernel_launch(void* const* d_in, const int* in_sizes, int n_in,
                              void* d_out, int out_size) {
    const float* x        = (const float*)d_in[0];
    const float* mem1_0   = (const float*)d_in[1];
    const float* mem2_0   = (const float*)d_in[2];
    const float* memo_0   = (const float*)d_in[3];
    const float* Wi1      = (const float*)d_in[4];
    const float* bi1      = (const float*)d_in[5];
    const float* W11      = (const float*)d_in[6];
    const float* b11      = (const float*)d_in[7];
    const float* W12      = (const float*)d_in[8];
    const float* b12      = (const float*)d_in[9];
    const float* W22      = (const float*)d_in[10];
    const float* b22      = (const float*)d_in[11];
    const float* Wo       = (const float*)d_in[12];
    const float* bo       = (const float*)d_in[13];
    const float* tau_adp1 = (const float*)d_in[14];
    const float* tau_adp2 = (const float*)d_in[15];
    const float* tau_m1   = (const float*)d_in[16];
    const float* tau_m2   = (const float*)d_in[17];
    const float* tau_mo   = (const float*)d_in[18];
    float* out = (float*)d_out;

    transpose_weights_kernel<<<(3 * H * H) / 256, 256>>>(W11, W12, W22);
    dim3 g(H / GBN, (BATCH * TT) / GBM);   // (2, 250)
    gemm_x1_kernel<<<g, 256>>>(x, Wi1, bi1, b11);
    rnn_kernel<<<BATCH / 4, 128>>>(mem1_0, mem2_0, memo_0, b12, b22, Wo, bo,
                                   tau_adp1, tau_adp2, tau_m1, tau_m2, tau_mo, out);
}

// round 5
// speedup vs baseline: 1.9255x; 1.9255x over previous
#include <cuda_runtime.h>
#include <math.h>

#define H 256
#define DIN 700
#define DOUT 20
#define BATCH 128
#define TT 250

// Scratch (device globals: allocation-free rule).
// Weight tables have an extra all-zero row (index 256) for padded gathers.
__device__ float g_X1[(size_t)BATCH * TT * H];   // x@Wi1.T + bi1 + b11
__device__ float g_W11T[(H + 1) * H];
__device__ float g_W12T[(H + 1) * H];
__device__ float g_W22T[(H + 1) * H];

// ---------------------------------------------------------------------------
// Packed fp32x2 FMA helpers (sm_103a FFMA2 — only reachable via PTX)
// ---------------------------------------------------------------------------
__device__ __forceinline__ void ffma2(unsigned long long& acc,
                                      unsigned long long a,
                                      unsigned long long b) {
    asm("fma.rn.f32x2 %0, %1, %2, %0;" : "+l"(acc) : "l"(a), "l"(b));
}
__device__ __forceinline__ unsigned long long pack2(float lo, float hi) {
    unsigned long long r;
    asm("mov.b64 %0, {%1, %2};" : "=l"(r) : "f"(lo), "f"(hi));
    return r;
}
__device__ __forceinline__ void unpack2(unsigned long long v, float& lo, float& hi) {
    asm("mov.b64 {%0, %1}, %2;" : "=f"(lo), "=f"(hi) : "l"(v));
}

// ---------------------------------------------------------------------------
// Weight transpose + zero row 256.
// ---------------------------------------------------------------------------
__global__ void transpose_weights_kernel(const float* __restrict__ W11,
                                         const float* __restrict__ W12,
                                         const float* __restrict__ W22) {
    int idx = blockIdx.x * blockDim.x + threadIdx.x;
    if (idx < 3 * H * H) {
        int m = idx >> 16;
        int r = (idx >> 8) & 255;
        int c = idx & 255;
        if (m == 0)      g_W11T[c * H + r] = W11[r * H + c];
        else if (m == 1) g_W12T[c * H + r] = W12[r * H + c];
        else             g_W22T[c * H + r] = W22[r * H + c];
    } else {
        int w = idx - 3 * H * H;        // 0..767: zero row 256 of each table
        if (w < 3 * H) {
            int m = w >> 8, c = w & 255;
            if (m == 0)      g_W11T[256 * H + c] = 0.f;
            else if (m == 1) g_W12T[256 * H + c] = 0.f;
            else             g_W22T[256 * H + c] = 0.f;
        }
    }
}

// ---------------------------------------------------------------------------
// X1 = x @ Wi1.T + (bi1 + b11).  M=32000, N=256, K=700.  (unchanged)
// ---------------------------------------------------------------------------
#define GBM 128
#define GBN 128
#define GBK 16
#define GPAD 4
#define GNT ((DIN + GBK - 1) / GBK)

__global__ __launch_bounds__(256) void gemm_x1_kernel(
    const float* __restrict__ x, const float* __restrict__ Wi1,
    const float* __restrict__ bi1, const float* __restrict__ b11) {
    __shared__ float As[2][GBK][GBM + GPAD];
    __shared__ float Bs[2][GBK][GBN + GPAD];

    int tid = threadIdx.x;
    int m0 = blockIdx.y * GBM;
    int n0 = blockIdx.x * GBN;
    int tx = tid & 15, ty = tid >> 4;

    int row0 = tid >> 2,          kc0 = tid & 3;
    int row1 = (256 + tid) >> 2,  kc1 = tid & 3;

    unsigned long long acc[4][8];
#pragma unroll
    for (int r = 0; r < 4; ++r)
#pragma unroll
        for (int c = 0; c < 8; ++c) acc[r][c] = 0ull;

    float4 stA0, stA1, stB0, stB1;

    {
        int kA0 = kc0 * 4, kA1 = kc1 * 4;
        stA0 = *(const float4*)(x   + (size_t)(m0 + row0) * DIN + kA0);
        stA1 = *(const float4*)(x   + (size_t)(m0 + row1) * DIN + kA1);
        stB0 = *(const float4*)(Wi1 + (size_t)(n0 + row0) * DIN + kA0);
        stB1 = *(const float4*)(Wi1 + (size_t)(n0 + row1) * DIN + kA1);
        As[0][kc0 * 4 + 0][row0] = stA0.x; As[0][kc0 * 4 + 1][row0] = stA0.y;
        As[0][kc0 * 4 + 2][row0] = stA0.z; As[0][kc0 * 4 + 3][row0] = stA0.w;
        As[0][kc1 * 4 + 0][row1] = stA1.x; As[0][kc1 * 4 + 1][row1] = stA1.y;
        As[0][kc1 * 4 + 2][row1] = stA1.z; As[0][kc1 * 4 + 3][row1] = stA1.w;
        Bs[0][kc0 * 4 + 0][row0] = stB0.x; Bs[0][kc0 * 4 + 1][row0] = stB0.y;
        Bs[0][kc0 * 4 + 2][row0] = stB0.z; Bs[0][kc0 * 4 + 3][row0] = stB0.w;
        Bs[0][kc1 * 4 + 0][row1] = stB1.x; Bs[0][kc1 * 4 + 1][row1] = stB1.y;
        Bs[0][kc1 * 4 + 2][row1] = stB1.z; Bs[0][kc1 * 4 + 3][row1] = stB1.w;
    }
    __syncthreads();

    for (int t = 0; t < GNT; ++t) {
        int buf = t & 1;

        if (t + 1 < GNT) {
            int kb = (t + 1) * GBK;
            int kA0 = kb + kc0 * 4, kA1 = kb + kc1 * 4;
            stA0 = (kA0 < DIN) ? *(const float4*)(x + (size_t)(m0 + row0) * DIN + kA0)
                               : make_float4(0.f, 0.f, 0.f, 0.f);
            stA1 = (kA1 < DIN) ? *(const float4*)(x + (size_t)(m0 + row1) * DIN + kA1)
                               : make_float4(0.f, 0.f, 0.f, 0.f);
            stB0 = (kA0 < DIN) ? *(const float4*)(Wi1 + (size_t)(n0 + row0) * DIN + kA0)
                               : make_float4(0.f, 0.f, 0.f, 0.f);
            stB1 = (kA1 < DIN) ? *(const float4*)(Wi1 + (size_t)(n0 + row1) * DIN + kA1)
                               : make_float4(0.f, 0.f, 0.f, 0.f);
        }

#pragma unroll
        for (int kk = 0; kk < GBK; ++kk) {
            ulonglong2 aA = *(const ulonglong2*)&As[buf][kk][ty * 8];
            ulonglong2 aB = *(const ulonglong2*)&As[buf][kk][ty * 8 + 4];
            float4 b0 = *(const float4*)&Bs[buf][kk][tx * 8];
            float4 b1 = *(const float4*)&Bs[buf][kk][tx * 8 + 4];
            float barr[8] = {b0.x, b0.y, b0.z, b0.w, b1.x, b1.y, b1.z, b1.w};
#pragma unroll
            for (int c = 0; c < 8; ++c) {
                unsigned long long bb = pack2(barr[c], barr[c]);
                ffma2(acc[0][c], aA.x, bb);
                ffma2(acc[1][c], aA.y, bb);
                ffma2(acc[2][c], aB.x, bb);
                ffma2(acc[3][c], aB.y, bb);
            }
        }

        if (t + 1 < GNT) {
            int nb = buf ^ 1;
            As[nb][kc0 * 4 + 0][row0] = stA0.x; As[nb][kc0 * 4 + 1][row0] = stA0.y;
            As[nb][kc0 * 4 + 2][row0] = stA0.z; As[nb][kc0 * 4 + 3][row0] = stA0.w;
            As[nb][kc1 * 4 + 0][row1] = stA1.x; As[nb][kc1 * 4 + 1][row1] = stA1.y;
            As[nb][kc1 * 4 + 2][row1] = stA1.z; As[nb][kc1 * 4 + 3][row1] = stA1.w;
            Bs[nb][kc0 * 4 + 0][row0] = stB0.x; Bs[nb][kc0 * 4 + 1][row0] = stB0.y;
            Bs[nb][kc0 * 4 + 2][row0] = stB0.z; Bs[nb][kc0 * 4 + 3][row0] = stB0.w;
            Bs[nb][kc1 * 4 + 0][row1] = stB1.x; Bs[nb][kc1 * 4 + 1][row1] = stB1.y;
            Bs[nb][kc1 * 4 + 2][row1] = stB1.z; Bs[nb][kc1 * 4 + 3][row1] = stB1.w;
        }
        __syncthreads();
    }

    float bias[8];
#pragma unroll
    for (int c = 0; c < 8; ++c) {
        int n = n0 + tx * 8 + c;
        bias[c] = bi1[n] + b11[n];
    }
#pragma unroll
    for (int r2 = 0; r2 < 4; ++r2) {
        float lo[8], hi[8];
#pragma unroll
        for (int c = 0; c < 8; ++c) unpack2(acc[r2][c], lo[c], hi[c]);
        int mA = m0 + ty * 8 + 2 * r2;
        int mB = mA + 1;
        int n = n0 + tx * 8;
        float4* pA = (float4*)(g_X1 + (size_t)mA * H + n);
        float4* pB = (float4*)(g_X1 + (size_t)mB * H + n);
        pA[0] = make_float4(lo[0] + bias[0], lo[1] + bias[1], lo[2] + bias[2], lo[3] + bias[3]);
        pA[1] = make_float4(lo[4] + bias[4], lo[5] + bias[5], lo[6] + bias[6], lo[7] + bias[7]);
        pB[0] = make_float4(hi[0] + bias[0], hi[1] + bias[1], hi[2] + bias[2], hi[3] + bias[3]);
        pB[1] = make_float4(hi[4] + bias[4], hi[5] + bias[5], hi[6] + bias[6], hi[7] + bias[7]);
    }
}

// ---------------------------------------------------------------------------
// Vectorized padded gathers. Thread (rep 0..7, slot 0..63) loads float4 slice
// [4*slot, 4*slot+4) of rows list[r*64 + rep + 8q], q=0..7. Pad index 256
// hits the zero row -> unconditional fixed-trip loops.
// ---------------------------------------------------------------------------
__device__ __forceinline__ void acc8(const float* __restrict__ W,
                                     const int* __restrict__ lst, int base,
                                     int col, float4& h) {
    int j0 = lst[base +  0], j1 = lst[base +  8], j2 = lst[base + 16], j3 = lst[base + 24];
    int j4 = lst[base + 32], j5 = lst[base + 40], j6 = lst[base + 48], j7 = lst[base + 56];
    float4 v0 = *(const float4*)(W + j0 * H + col);
    float4 v1 = *(const float4*)(W + j1 * H + col);
    float4 v2 = *(const float4*)(W + j2 * H + col);
    float4 v3 = *(const float4*)(W + j3 * H + col);
    float4 v4 = *(const float4*)(W + j4 * H + col);
    float4 v5 = *(const float4*)(W + j5 * H + col);
    float4 v6 = *(const float4*)(W + j6 * H + col);
    float4 v7 = *(const float4*)(W + j7 * H + col);
    h.x += ((v0.x + v1.x) + (v2.x + v3.x)) + ((v4.x + v5.x) + (v6.x + v7.x));
    h.y += ((v0.y + v1.y) + (v2.y + v3.y)) + ((v4.y + v5.y) + (v6.y + v7.y));
    h.z += ((v0.z + v1.z) + (v2.z + v3.z)) + ((v4.z + v5.z) + (v6.z + v7.z));
    h.w += ((v0.w + v1.w) + (v2.w + v3.w)) + ((v4.w + v5.w) + (v6.w + v7.w));
}

// ---------------------------------------------------------------------------
// Persistent RNN: one CTA per sample, 512 threads.
// Owners = threads 0..255 (neuron i = tid); all 512 threads gather.
// ---------------------------------------------------------------------------
__global__ __launch_bounds__(512) void rnn_kernel(
    const float* __restrict__ mem1_0, const float* __restrict__ mem2_0,
    const float* __restrict__ memo_0,
    const float* __restrict__ b12v, const float* __restrict__ b22v,
    const float* __restrict__ Wo, const float* __restrict__ bov,
    const float* __restrict__ tau_adp1, const float* __restrict__ tau_adp2,
    const float* __restrict__ tau_m1, const float* __restrict__ tau_m2,
    const float* __restrict__ tau_mo,
    float* __restrict__ out) {
    __shared__ __align__(16) int list1[2][H];
    __shared__ __align__(16) int list2[2][H];
    __shared__ unsigned mb1[8], mb2[8];
    __shared__ float part11[8][H];
    __shared__ float part22[8][H];
    __shared__ float part12[8][H];
    __shared__ float sWoT[H * DOUT];

    int b = blockIdx.x;
    int tid = threadIdx.x;
    int lane = tid & 31, warp = tid >> 5;
    int rep = tid >> 6;        // 0..7
    int slot = tid & 63;       // 0..63
    int col = slot << 2;       // float4 column offset

    // ---- one-time init ----
    for (int idx = tid; idx < H * DOUT; idx += 512) {
        int j = idx / DOUT, k = idx - j * DOUT;
        sWoT[idx] = Wo[k * H + j];
    }
    if (tid < H) {
        list1[0][tid] = 256; list1[1][tid] = 256;
        list2[0][tid] = 256; list2[1][tid] = 256;
    }

    // owner (tid < 256) per-neuron state
    float mem1 = 0.f, sp1 = 0.f, ab1 = 0.01f, al1 = 0.f, ro1 = 0.f;
    float mem2 = 0.f, sp2 = 0.f, ab2 = 0.01f, al2 = 0.f, ro2 = 0.f;
    float hb2 = 0.f;
    float memo = 0.f, alo = 0.f, omo = 0.f, bok = 0.f, accv = 0.f;
    if (tid < 256) {
        mem1 = mem1_0[b * H + tid];
        al1 = expf(-1.f / tau_m1[tid]);
        ro1 = expf(-1.f / tau_adp1[tid]);
        mem2 = mem2_0[b * H + tid];
        al2 = expf(-1.f / tau_m2[tid]);
        ro2 = expf(-1.f / tau_adp2[tid]);
        hb2 = b12v[tid] + b22v[tid];
        if (tid < DOUT) {
            memo = memo_0[b * DOUT + tid];
            alo = expf(-1.f / tau_mo[tid]); omo = 1.f - alo;
            bok = bov[tid];
        }
    }
    __syncthreads();

    int cnt1 = 0, cnt2 = 0, p = 0;
    const float* X1base = g_X1 + (size_t)b * TT * H;

    float x1cur = (tid < 256) ? X1base[tid] : 0.f;

    for (int t = 0; t < TT; ++t) {
        int pn = p ^ 1;

        // prefetch next X1 (owners)
        float x1nxt = 0.f;
        if (tid < 256 && t + 1 < TT) x1nxt = X1base[(t + 1) * H + tid];

        // ---- phase A: fused W11 (old sp1) + W22 (old sp2) gather ----
        {
            int nrA = (cnt1 > cnt2 ? cnt1 : cnt2);
            nrA = (nrA + 63) >> 6; if (nrA < 1) nrA = 1;
            float4 a11 = make_float4(0.f, 0.f, 0.f, 0.f);
            float4 a22 = make_float4(0.f, 0.f, 0.f, 0.f);
            for (int r = 0; r < nrA; ++r) {
                int base = (r << 6) + rep;
                acc8(g_W11T, list1[p], base, col, a11);
                acc8(g_W22T, list2[p], base, col, a22);
            }
            *(float4*)&part11[rep][col] = a11;
            *(float4*)&part22[rep][col] = a22;
        }
        __syncthreads();   // (a)

        // ---- layer 1 update (owners) + pad + ballot ----
        float sp1n = 0.f;
        if (tid < 256) {
            float h1 = x1cur;
#pragma unroll
            for (int r = 0; r < 8; ++r) h1 += part11[r][tid];
            ab1 = ro1 * ab1 + (1.f - ro1) * sp1;
            float B = 0.01f + 1.8f * ab1;
            mem1 = mem1 * al1 + (1.f - al1) * h1 - B * sp1;
            sp1n = (mem1 - B) > 0.f ? 1.f : 0.f;
            list1[pn][tid] = 256;                       // pad (overwritten below)
            unsigned bal = __ballot_sync(0xffffffffu, sp1n != 0.f);
            if (lane == 0) mb1[warp] = bal;
        }
        __syncthreads();   // (b)

        int cnt1n;
        {
            int base = 0, tot = 0;
#pragma unroll
            for (int w = 0; w < 8; ++w) {
                int c = __popc(mb1[w]);
                if (w < warp) base += c;
                tot += c;
            }
            if (tid < 256 && sp1n != 0.f) {
                unsigned bal = mb1[warp];
                list1[pn][base + __popc(bal & ((1u << lane) - 1u))] = tid;
            }
            cnt1n = tot;
        }
        __syncthreads();   // (c)

        // ---- phase B: W12 gather (new sp1) ----
        {
            int nrB = (cnt1n + 63) >> 6; if (nrB < 1) nrB = 1;
            float4 a12 = make_float4(0.f, 0.f, 0.f, 0.f);
            for (int r = 0; r < nrB; ++r)
                acc8(g_W12T, list1[pn], (r << 6) + rep, col, a12);
            *(float4*)&part12[rep][col] = a12;
        }
        __syncthreads();   // (d)

        // ---- layer 2 update (owners) + pad + ballot ----
        float sp2n = 0.f;
        if (tid < 256) {
            float h2 = hb2;
#pragma unroll
            for (int r = 0; r < 8; ++r) h2 += part12[r][tid];
#pragma unroll
            for (int r = 0; r < 8; ++r) h2 += part22[r][tid];
            ab2 = ro2 * ab2 + (1.f - ro2) * sp2;
            float B = 0.01f + 1.8f * ab2;
            mem2 = mem2 * al2 + (1.f - al2) * h2 - B * sp2;
            sp2n = (mem2 - B) > 0.f ? 1.f : 0.f;
            list2[pn][tid] = 256;                       // pad
            unsigned bal = __ballot_sync(0xffffffffu, sp2n != 0.f);
            if (lane == 0) mb2[warp] = bal;
        }
        __syncthreads();   // (e)

        int cnt2n;
        {
            int base = 0, tot = 0;
#pragma unroll
            for (int w = 0; w < 8; ++w) {
                int c = __popc(mb2[w]);
                if (w < warp) base += c;
                tot += c;
            }
            if (tid < 256 && sp2n != 0.f) {
                unsigned bal = mb2[warp];
                list2[pn][base + __popc(bal & ((1u << lane) - 1u))] = tid;
            }
            cnt2n = tot;
        }
        __syncthreads();   // (f)

        // ---- output layer + softmax accumulation (warp 0); other warps
        //      run ahead into next step's phase A ----
        if (warp == 0) {
            int kk = lane < DOUT ? lane : 0;
            float o = bok;
            const int* l2 = list2[pn];
            for (int q = 0; q < cnt2n; ++q) o += sWoT[l2[q] * DOUT + kk];
            memo = memo * alo + omo * o;
            float mv = lane < DOUT ? memo : -INFINITY;
#pragma unroll
            for (int sh = 16; sh > 0; sh >>= 1)
                mv = fmaxf(mv, __shfl_xor_sync(0xffffffffu, mv, sh));
            float e = lane < DOUT ? expf(memo - mv) : 0.f;
            float ss = e;
#pragma unroll
            for (int sh = 16; sh > 0; sh >>= 1)
                ss += __shfl_xor_sync(0xffffffffu, ss, sh);
            if (t > 10) accv += e / ss;
        }

        sp1 = sp1n; sp2 = sp2n; cnt1 = cnt1n; cnt2 = cnt2n; p = pn;
        x1cur = x1nxt;
    }

    if (tid < DOUT) out[b * DOUT + tid] = accv;
}

// ---------------------------------------------------------------------------
extern "C" void kernel_launch(void* const* d_in, const int* in_sizes, int n_in,
                              void* d_out, int out_size) {
    const float* x        = (const float*)d_in[0];
    const float* mem1_0   = (const float*)d_in[1];
    const float* mem2_0   = (const float*)d_in[2];
    const float* memo_0   = (const float*)d_in[3];
    const float* Wi1      = (const float*)d_in[4];
    const float* bi1      = (const float*)d_in[5];
    const float* W11      = (const float*)d_in[6];
    const float* b11      = (const float*)d_in[7];
    const float* W12      = (const float*)d_in[8];
    const float* b12      = (const float*)d_in[9];
    const float* W22      = (const float*)d_in[10];
    const float* b22      = (const float*)d_in[11];
    const float* Wo       = (const float*)d_in[12];
    const float* bo       = (const float*)d_in[13];
    const float* tau_adp1 = (const float*)d_in[14];
    const float* tau_adp2 = (const float*)d_in[15];
    const float* tau_m1   = (const float*)d_in[16];
    const float* tau_m2   = (const float*)d_in[17];
    const float* tau_mo   = (const float*)d_in[18];
    float* out = (float*)d_out;

    transpose_weights_kernel<<<(3 * H * H + 3 * H + 255) / 256, 256>>>(W11, W12, W22);
    dim3 g(H / GBN, (BATCH * TT) / GBM);   // (2, 250)
    gemm_x1_kernel<<<g, 256>>>(x, Wi1, bi1, b11);
    rnn_kernel<<<BATCH, 512>>>(mem1_0, mem2_0, memo_0, b12, b22, Wo, bo,
                               tau_adp1, tau_adp2, tau_m1, tau_m2, tau_mo, out);
}

// round 6
// speedup vs baseline: 2.0016x; 1.0395x over previous
#include <cuda_runtime.h>
#include <math.h>

#define H 256
#define DIN 700
#define DOUT 20
#define BATCH 128
#define TT 250

// Scratch (device globals: allocation-free rule).
// g_X1 is T-MAJOR: X1[t][b][i]  (t*BATCH*H + b*H + i)
// Weight tables have an extra all-zero row (index 256) for padded gathers.
__device__ float g_X1[(size_t)TT * BATCH * H];
__device__ float g_W11T[(H + 1) * H];
__device__ float g_W12T[(H + 1) * H];
__device__ float g_W22T[(H + 1) * H];
__device__ int   g_ready[TT];      // 2 == timestep t of X1 complete

// ---------------------------------------------------------------------------
__device__ __forceinline__ void ffma2(unsigned long long& acc,
                                      unsigned long long a,
                                      unsigned long long b) {
    asm("fma.rn.f32x2 %0, %1, %2, %0;" : "+l"(acc) : "l"(a), "l"(b));
}
__device__ __forceinline__ unsigned long long pack2(float lo, float hi) {
    unsigned long long r;
    asm("mov.b64 %0, {%1, %2};" : "=l"(r) : "f"(lo), "f"(hi));
    return r;
}
__device__ __forceinline__ void unpack2(unsigned long long v, float& lo, float& hi) {
    asm("mov.b64 {%0, %1}, %2;" : "=f"(lo), "=f"(hi) : "l"(v));
}
__device__ __forceinline__ int ld_acquire(const int* p) {
    int v;
    asm volatile("ld.acquire.gpu.b32 %0, [%1];" : "=r"(v) : "l"(p) : "memory");
    return v;
}

// ---------------------------------------------------------------------------
__global__ void clear_flags_kernel() {
    int i = threadIdx.x + blockIdx.x * blockDim.x;
    if (i < TT) g_ready[i] = 0;
}

// ---------------------------------------------------------------------------
// Weight transpose + zero row 256.
// ---------------------------------------------------------------------------
__global__ void transpose_weights_kernel(const float* __restrict__ W11,
                                         const float* __restrict__ W12,
                                         const float* __restrict__ W22) {
    int idx = blockIdx.x * blockDim.x + threadIdx.x;
    if (idx < 3 * H * H) {
        int m = idx >> 16;
        int r = (idx >> 8) & 255;
        int c = idx & 255;
        if (m == 0)      g_W11T[c * H + r] = W11[r * H + c];
        else if (m == 1) g_W12T[c * H + r] = W12[r * H + c];
        else             g_W22T[c * H + r] = W22[r * H + c];
    } else {
        int w = idx - 3 * H * H;
        if (w < 3 * H) {
            int m = w >> 8, c = w & 255;
            if (m == 0)      g_W11T[256 * H + c] = 0.f;
            else if (m == 1) g_W12T[256 * H + c] = 0.f;
            else             g_W22T[256 * H + c] = 0.f;
        }
    }
}

// ---------------------------------------------------------------------------
// X1[t][b][:] = x[b][t][:] @ Wi1.T + (bi1 + b11).
// Block y == timestep t (GBM == BATCH == 128). Sets g_ready[t] when done.
// ---------------------------------------------------------------------------
#define GBM 128
#define GBN 128
#define GBK 16
#define GPAD 4
#define GNT ((DIN + GBK - 1) / GBK)

__global__ __launch_bounds__(256) void gemm_x1_kernel(
    const float* __restrict__ x, const float* __restrict__ Wi1,
    const float* __restrict__ bi1, const float* __restrict__ b11) {
    __shared__ float As[2][GBK][GBM + GPAD];
    __shared__ float Bs[2][GBK][GBN + GPAD];

    int tid = threadIdx.x;
    int tstep = blockIdx.y;            // timestep
    int n0 = blockIdx.x * GBN;
    int tx = tid & 15, ty = tid >> 4;

    int row0 = tid >> 2,          kc0 = tid & 3;   // row = sample b
    int row1 = (256 + tid) >> 2,  kc1 = tid & 3;

    const float* xr0 = x + ((size_t)row0 * TT + tstep) * DIN;
    const float* xr1 = x + ((size_t)row1 * TT + tstep) * DIN;

    unsigned long long acc[4][8];
#pragma unroll
    for (int r = 0; r < 4; ++r)
#pragma unroll
        for (int c = 0; c < 8; ++c) acc[r][c] = 0ull;

    float4 stA0, stA1, stB0, stB1;

    {
        int kA0 = kc0 * 4, kA1 = kc1 * 4;
        stA0 = *(const float4*)(xr0 + kA0);
        stA1 = *(const float4*)(xr1 + kA1);
        stB0 = *(const float4*)(Wi1 + (size_t)(n0 + row0) * DIN + kA0);
        stB1 = *(const float4*)(Wi1 + (size_t)(n0 + row1) * DIN + kA1);
        As[0][kc0 * 4 + 0][row0] = stA0.x; As[0][kc0 * 4 + 1][row0] = stA0.y;
        As[0][kc0 * 4 + 2][row0] = stA0.z; As[0][kc0 * 4 + 3][row0] = stA0.w;
        As[0][kc1 * 4 + 0][row1] = stA1.x; As[0][kc1 * 4 + 1][row1] = stA1.y;
        As[0][kc1 * 4 + 2][row1] = stA1.z; As[0][kc1 * 4 + 3][row1] = stA1.w;
        Bs[0][kc0 * 4 + 0][row0] = stB0.x; Bs[0][kc0 * 4 + 1][row0] = stB0.y;
        Bs[0][kc0 * 4 + 2][row0] = stB0.z; Bs[0][kc0 * 4 + 3][row0] = stB0.w;
        Bs[0][kc1 * 4 + 0][row1] = stB1.x; Bs[0][kc1 * 4 + 1][row1] = stB1.y;
        Bs[0][kc1 * 4 + 2][row1] = stB1.z; Bs[0][kc1 * 4 + 3][row1] = stB1.w;
    }
    __syncthreads();

    for (int t = 0; t < GNT; ++t) {
        int buf = t & 1;

        if (t + 1 < GNT) {
            int kb = (t + 1) * GBK;
            int kA0 = kb + kc0 * 4, kA1 = kb + kc1 * 4;
            stA0 = (kA0 < DIN) ? *(const float4*)(xr0 + kA0) : make_float4(0.f,0.f,0.f,0.f);
            stA1 = (kA1 < DIN) ? *(const float4*)(xr1 + kA1) : make_float4(0.f,0.f,0.f,0.f);
            stB0 = (kA0 < DIN) ? *(const float4*)(Wi1 + (size_t)(n0 + row0) * DIN + kA0)
                               : make_float4(0.f, 0.f, 0.f, 0.f);
            stB1 = (kA1 < DIN) ? *(const float4*)(Wi1 + (size_t)(n0 + row1) * DIN + kA1)
                               : make_float4(0.f, 0.f, 0.f, 0.f);
        }

#pragma unroll
        for (int kk = 0; kk < GBK; ++kk) {
            ulonglong2 aA = *(const ulonglong2*)&As[buf][kk][ty * 8];
            ulonglong2 aB = *(const ulonglong2*)&As[buf][kk][ty * 8 + 4];
            float4 b0 = *(const float4*)&Bs[buf][kk][tx * 8];
            float4 b1 = *(const float4*)&Bs[buf][kk][tx * 8 + 4];
            float barr[8] = {b0.x, b0.y, b0.z, b0.w, b1.x, b1.y, b1.z, b1.w};
#pragma unroll
            for (int c = 0; c < 8; ++c) {
                unsigned long long bb = pack2(barr[c], barr[c]);
                ffma2(acc[0][c], aA.x, bb);
                ffma2(acc[1][c], aA.y, bb);
                ffma2(acc[2][c], aB.x, bb);
                ffma2(acc[3][c], aB.y, bb);
            }
        }

        if (t + 1 < GNT) {
            int nb = buf ^ 1;
            As[nb][kc0 * 4 + 0][row0] = stA0.x; As[nb][kc0 * 4 + 1][row0] = stA0.y;
            As[nb][kc0 * 4 + 2][row0] = stA0.z; As[nb][kc0 * 4 + 3][row0] = stA0.w;
            As[nb][kc1 * 4 + 0][row1] = stA1.x; As[nb][kc1 * 4 + 1][row1] = stA1.y;
            As[nb][kc1 * 4 + 2][row1] = stA1.z; As[nb][kc1 * 4 + 3][row1] = stA1.w;
            Bs[nb][kc0 * 4 + 0][row0] = stB0.x; Bs[nb][kc0 * 4 + 1][row0] = stB0.y;
            Bs[nb][kc0 * 4 + 2][row0] = stB0.z; Bs[nb][kc0 * 4 + 3][row0] = stB0.w;
            Bs[nb][kc1 * 4 + 0][row1] = stB1.x; Bs[nb][kc1 * 4 + 1][row1] = stB1.y;
            Bs[nb][kc1 * 4 + 2][row1] = stB1.z; Bs[nb][kc1 * 4 + 3][row1] = stB1.w;
        }
        __syncthreads();
    }

    float bias[8];
#pragma unroll
    for (int c = 0; c < 8; ++c) {
        int n = n0 + tx * 8 + c;
        bias[c] = bi1[n] + b11[n];
    }
    float* X1t = g_X1 + (size_t)tstep * BATCH * H;
#pragma unroll
    for (int r2 = 0; r2 < 4; ++r2) {
        float lo[8], hi[8];
#pragma unroll
        for (int c = 0; c < 8; ++c) unpack2(acc[r2][c], lo[c], hi[c]);
        int bA = ty * 8 + 2 * r2;       // sample index
        int bB = bA + 1;
        int n = n0 + tx * 8;
        float4* pA = (float4*)(X1t + (size_t)bA * H + n);
        float4* pB = (float4*)(X1t + (size_t)bB * H + n);
        pA[0] = make_float4(lo[0] + bias[0], lo[1] + bias[1], lo[2] + bias[2], lo[3] + bias[3]);
        pA[1] = make_float4(lo[4] + bias[4], lo[5] + bias[5], lo[6] + bias[6], lo[7] + bias[7]);
        pB[0] = make_float4(hi[0] + bias[0], hi[1] + bias[1], hi[2] + bias[2], hi[3] + bias[3]);
        pB[1] = make_float4(hi[4] + bias[4], hi[5] + bias[5], hi[6] + bias[6], hi[7] + bias[7]);
    }

    // publish readiness
    __threadfence();
    __syncthreads();
    if (tid == 0) atomicAdd(&g_ready[tstep], 1);
}

// ---------------------------------------------------------------------------
// Vectorized padded gathers (unchanged from R5).
// ---------------------------------------------------------------------------
__device__ __forceinline__ void acc8(const float* __restrict__ W,
                                     const int* __restrict__ lst, int base,
                                     int col, float4& h) {
    int j0 = lst[base +  0], j1 = lst[base +  8], j2 = lst[base + 16], j3 = lst[base + 24];
    int j4 = lst[base + 32], j5 = lst[base + 40], j6 = lst[base + 48], j7 = lst[base + 56];
    float4 v0 = *(const float4*)(W + j0 * H + col);
    float4 v1 = *(const float4*)(W + j1 * H + col);
    float4 v2 = *(const float4*)(W + j2 * H + col);
    float4 v3 = *(const float4*)(W + j3 * H + col);
    float4 v4 = *(const float4*)(W + j4 * H + col);
    float4 v5 = *(const float4*)(W + j5 * H + col);
    float4 v6 = *(const float4*)(W + j6 * H + col);
    float4 v7 = *(const float4*)(W + j7 * H + col);
    h.x += ((v0.x + v1.x) + (v2.x + v3.x)) + ((v4.x + v5.x) + (v6.x + v7.x));
    h.y += ((v0.y + v1.y) + (v2.y + v3.y)) + ((v4.y + v5.y) + (v6.y + v7.y));
    h.z += ((v0.z + v1.z) + (v2.z + v3.z)) + ((v4.z + v5.z) + (v6.z + v7.z));
    h.w += ((v0.w + v1.w) + (v2.w + v3.w)) + ((v4.w + v5.w) + (v6.w + v7.w));
}

// ---------------------------------------------------------------------------
// Persistent RNN: one CTA per sample, 512 threads. Spins on g_ready[t]
// before consuming X1[t] (GEMM runs concurrently on another stream).
// ---------------------------------------------------------------------------
__global__ __launch_bounds__(512) void rnn_kernel(
    const float* __restrict__ mem1_0, const float* __restrict__ mem2_0,
    const float* __restrict__ memo_0,
    const float* __restrict__ b12v, const float* __restrict__ b22v,
    const float* __restrict__ Wo, const float* __restrict__ bov,
    const float* __restrict__ tau_adp1, const float* __restrict__ tau_adp2,
    const float* __restrict__ tau_m1, const float* __restrict__ tau_m2,
    const float* __restrict__ tau_mo,
    float* __restrict__ out) {
    __shared__ __align__(16) int list1[2][H];
    __shared__ __align__(16) int list2[2][H];
    __shared__ unsigned mb1[8], mb2[8];
    __shared__ float part11[8][H];
    __shared__ float part22[8][H];
    __shared__ float part12[8][H];
    __shared__ float sWoT[(H + 1) * DOUT];   // zero row 256 for padded output loop

    int b = blockIdx.x;
    int tid = threadIdx.x;
    int lane = tid & 31, warp = tid >> 5;
    int rep = tid >> 6;
    int slot = tid & 63;
    int col = slot << 2;

    for (int idx = tid; idx < H * DOUT; idx += 512) {
        int j = idx / DOUT, k = idx - j * DOUT;
        sWoT[idx] = Wo[k * H + j];
    }
    if (tid < DOUT) sWoT[H * DOUT + tid] = 0.f;
    if (tid < H) {
        list1[0][tid] = 256; list1[1][tid] = 256;
        list2[0][tid] = 256; list2[1][tid] = 256;
    }

    float mem1 = 0.f, sp1 = 0.f, ab1 = 0.01f, al1 = 0.f, ro1 = 0.f;
    float mem2 = 0.f, sp2 = 0.f, ab2 = 0.01f, al2 = 0.f, ro2 = 0.f;
    float hb2 = 0.f;
    float memo = 0.f, alo = 0.f, omo = 0.f, bok = 0.f, accv = 0.f;
    if (tid < 256) {
        mem1 = mem1_0[b * H + tid];
        al1 = expf(-1.f / tau_m1[tid]);
        ro1 = expf(-1.f / tau_adp1[tid]);
        mem2 = mem2_0[b * H + tid];
        al2 = expf(-1.f / tau_m2[tid]);
        ro2 = expf(-1.f / tau_adp2[tid]);
        hb2 = b12v[tid] + b22v[tid];
        if (tid < DOUT) {
            memo = memo_0[b * DOUT + tid];
            alo = expf(-1.f / tau_mo[tid]); omo = 1.f - alo;
            bok = bov[tid];
        }
    }
    __syncthreads();

    int cnt1 = 0, cnt2 = 0, p = 0;

    float x1cur = 0.f;
    if (tid < 256) {
        while (ld_acquire(&g_ready[0]) < 2) __nanosleep(64);
        x1cur = g_X1[(size_t)b * H + tid];
    }

    for (int t = 0; t < TT; ++t) {
        int pn = p ^ 1;

        float x1nxt = 0.f;
        if (tid < 256 && t + 1 < TT) {
            while (ld_acquire(&g_ready[t + 1]) < 2) __nanosleep(64);
            x1nxt = g_X1[((size_t)(t + 1) * BATCH + b) * H + tid];
        }

        // ---- phase A: fused W11 (old sp1) + W22 (old sp2) gather ----
        {
            int nrA = (cnt1 > cnt2 ? cnt1 : cnt2);
            nrA = (nrA + 63) >> 6; if (nrA < 1) nrA = 1;
            float4 a11 = make_float4(0.f, 0.f, 0.f, 0.f);
            float4 a22 = make_float4(0.f, 0.f, 0.f, 0.f);
            for (int r = 0; r < nrA; ++r) {
                int base = (r << 6) + rep;
                acc8(g_W11T, list1[p], base, col, a11);
                acc8(g_W22T, list2[p], base, col, a22);
            }
            *(float4*)&part11[rep][col] = a11;
            *(float4*)&part22[rep][col] = a22;
        }
        __syncthreads();   // (a)

        float sp1n = 0.f;
        if (tid < 256) {
            float h1 = x1cur;
#pragma unroll
            for (int r = 0; r < 8; ++r) h1 += part11[r][tid];
            ab1 = ro1 * ab1 + (1.f - ro1) * sp1;
            float B = 0.01f + 1.8f * ab1;
            mem1 = mem1 * al1 + (1.f - al1) * h1 - B * sp1;
            sp1n = (mem1 - B) > 0.f ? 1.f : 0.f;
            list1[pn][tid] = 256;
            unsigned bal = __ballot_sync(0xffffffffu, sp1n != 0.f);
            if (lane == 0) mb1[warp] = bal;
        }
        __syncthreads();   // (b)

        int cnt1n;
        {
            int base = 0, tot = 0;
#pragma unroll
            for (int w = 0; w < 8; ++w) {
                int c = __popc(mb1[w]);
                if (w < warp) base += c;
                tot += c;
            }
            if (tid < 256 && sp1n != 0.f) {
                unsigned bal = mb1[warp];
                list1[pn][base + __popc(bal & ((1u << lane) - 1u))] = tid;
            }
            cnt1n = tot;
        }
        __syncthreads();   // (c)

        // ---- phase B: W12 gather (new sp1) ----
        {
            int nrB = (cnt1n + 63) >> 6; if (nrB < 1) nrB = 1;
            float4 a12 = make_float4(0.f, 0.f, 0.f, 0.f);
            for (int r = 0; r < nrB; ++r)
                acc8(g_W12T, list1[pn], (r << 6) + rep, col, a12);
            *(float4*)&part12[rep][col] = a12;
        }
        __syncthreads();   // (d)

        float sp2n = 0.f;
        if (tid < 256) {
            float h2 = hb2;
#pragma unroll
            for (int r = 0; r < 8; ++r) h2 += part12[r][tid];
#pragma unroll
            for (int r = 0; r < 8; ++r) h2 += part22[r][tid];
            ab2 = ro2 * ab2 + (1.f - ro2) * sp2;
            float B = 0.01f + 1.8f * ab2;
            mem2 = mem2 * al2 + (1.f - al2) * h2 - B * sp2;
            sp2n = (mem2 - B) > 0.f ? 1.f : 0.f;
            list2[pn][tid] = 256;
            unsigned bal = __ballot_sync(0xffffffffu, sp2n != 0.f);
            if (lane == 0) mb2[warp] = bal;
        }
        __syncthreads();   // (e)

        int cnt2n;
        {
            int base = 0, tot = 0;
#pragma unroll
            for (int w = 0; w < 8; ++w) {
                int c = __popc(mb2[w]);
                if (w < warp) base += c;
                tot += c;
            }
            if (tid < 256 && sp2n != 0.f) {
                unsigned bal = mb2[warp];
                list2[pn][base + __popc(bal & ((1u << lane) - 1u))] = tid;
            }
            cnt2n = tot;
        }
        __syncthreads();   // (f)

        // ---- output layer + softmax accumulation (warp 0) ----
        if (warp == 0) {
            int kk = lane < DOUT ? lane : 0;
            float o0 = bok, o1 = 0.f, o2 = 0.f, o3 = 0.f;
            const int* l2 = list2[pn];
            int nq = (cnt2n + 3) & ~3;      // pads hit zero row 256
            for (int q = 0; q < nq; q += 4) {
                o0 += sWoT[l2[q + 0] * DOUT + kk];
                o1 += sWoT[l2[q + 1] * DOUT + kk];
                o2 += sWoT[l2[q + 2] * DOUT + kk];
                o3 += sWoT[l2[q + 3] * DOUT + kk];
            }
            float o = (o0 + o1) + (o2 + o3);
            memo = memo * alo + omo * o;
            float mv = lane < DOUT ? memo : -INFINITY;
#pragma unroll
            for (int sh = 16; sh > 0; sh >>= 1)
                mv = fmaxf(mv, __shfl_xor_sync(0xffffffffu, mv, sh));
            float e = lane < DOUT ? expf(memo - mv) : 0.f;
            float ss = e;
#pragma unroll
            for (int sh = 16; sh > 0; sh >>= 1)
                ss += __shfl_xor_sync(0xffffffffu, ss, sh);
            if (t > 10) accv += e / ss;
        }

        sp1 = sp1n; sp2 = sp2n; cnt1 = cnt1n; cnt2 = cnt2n; p = pn;
        x1cur = x1nxt;
    }

    if (tid < DOUT) out[b * DOUT + tid] = accv;
}

// ---------------------------------------------------------------------------
extern "C" void kernel_launch(void* const* d_in, const int* in_sizes, int n_in,
                              void* d_out, int out_size) {
    const float* x        = (const float*)d_in[0];
    const float* mem1_0   = (const float*)d_in[1];
    const float* mem2_0   = (const float*)d_in[2];
    const float* memo_0   = (const float*)d_in[3];
    const float* Wi1      = (const float*)d_in[4];
    const float* bi1      = (const float*)d_in[5];
    const float* W11      = (const float*)d_in[6];
    const float* b11      = (const float*)d_in[7];
    const float* W12      = (const float*)d_in[8];
    const float* b12      = (const float*)d_in[9];
    const float* W22      = (const float*)d_in[10];
    const float* b22      = (const float*)d_in[11];
    const float* Wo       = (const float*)d_in[12];
    const float* bo       = (const float*)d_in[13];
    const float* tau_adp1 = (const float*)d_in[14];
    const float* tau_adp2 = (const float*)d_in[15];
    const float* tau_m1   = (const float*)d_in[16];
    const float* tau_m2   = (const float*)d_in[17];
    const float* tau_mo   = (const float*)d_in[18];
    float* out = (float*)d_out;

    // Fork the GEMM onto a side stream so it overlaps the RNN. Host-side
    // stream/event creation is allowed (no device memory involved).
    cudaStream_t s2 = 0;
    cudaEvent_t evFork = 0, evJoin = 0;
    bool forked =
        (cudaStreamCreateWithFlags(&s2, cudaStreamNonBlocking) == cudaSuccess) &&
        (cudaEventCreateWithFlags(&evFork, cudaEventDisableTiming) == cudaSuccess) &&
        (cudaEventCreateWithFlags(&evJoin, cudaEventDisableTiming) == cudaSuccess);

    clear_flags_kernel<<<1, 256>>>();

    dim3 g(H / GBN, TT);   // (2, 250): block y == timestep
    if (forked && cudaEventRecord(evFork, 0) == cudaSuccess &&
        cudaStreamWaitEvent(s2, evFork, 0) == cudaSuccess) {
        gemm_x1_kernel<<<g, 256, 0, s2>>>(x, Wi1, bi1, b11);
        cudaEventRecord(evJoin, s2);
    } else {
        gemm_x1_kernel<<<g, 256>>>(x, Wi1, bi1, b11);
        forked = false;
    }

    transpose_weights_kernel<<<(3 * H * H + 3 * H + 255) / 256, 256>>>(W11, W12, W22);
    rnn_kernel<<<BATCH, 512>>>(mem1_0, mem2_0, memo_0, b12, b22, Wo, bo,
                               tau_adp1, tau_adp2, tau_m1, tau_m2, tau_mo, out);

    if (forked) cudaStreamWaitEvent(0, evJoin, 0);   // join for clean capture

    if (evFork) cudaEventDestroy(evFork);
    if (evJoin) cudaEventDestroy(evJoin);
    if (s2) cudaStreamDestroy(s2);
}